// round 1
// baseline (speedup 1.0000x reference)
#include <cuda_runtime.h>
#include <math.h>

#define Bsz 128
#define Nn  512
#define Dd  64
#define KTOP 20
#define FULLMASK 0xFFFFFFFFu
#define NEG_SLOPE 0.2f
#define BN_EPS 1e-5f

// ---------------- scratch (device globals; no allocations) ----------------
__device__ float g_z[Bsz*Nn*Dd];     // 16.7 MB
__device__ float g_rst[Bsz*Nn*Dd];   // 16.7 MB
__device__ float g_cos[Nn*Nn];       // 1 MB
__device__ int   g_topk[Nn*KTOP];
__device__ float g_rnrm[Nn];
__device__ float g_esrc[Nn];
__device__ float g_edst[Nn];
__device__ float g_sum[Dd];
__device__ float g_sumsq[Dd];
__device__ float g_scale[Dd];
__device__ float g_shift[Dd];

// ---------------- K0: per-node precompute + zero accumulators -------------
__global__ void k0_prep(const float* __restrict__ emb,
                        const float* __restrict__ attn_w) {
    int n = threadIdx.x;             // 512 threads
    if (n < Dd) { g_sum[n] = 0.f; g_sumsq[n] = 0.f; }
    const float* e = emb + n * Dd;
    float s = 0.f, es = 0.f, ed = 0.f;
#pragma unroll
    for (int k = 0; k < Dd; ++k) {
        float v = e[k];
        s  += v * v;
        es += v * attn_w[Dd + k];        // a_src, emb half: attn_w[64..127]
        ed += v * attn_w[3*Dd + k];      // a_dst, emb half: attn_w[192..255]
    }
    g_rnrm[n] = 1.0f / sqrtf(s);
    g_esrc[n] = es;
    g_edst[n] = ed;
}

// ---------------- K1: cosine Gram matrix (512x512x64 GEMM) ----------------
__global__ void k1_cos(const float* __restrict__ emb) {
    __shared__ float At[64*68];
    __shared__ float Bt[64*68];
    int i0 = blockIdx.y * 64, j0 = blockIdx.x * 64;
    int tid = threadIdx.x;           // 256 threads
    for (int idx = tid; idx < 4096; idx += 256) {
        int r = idx >> 6, k = idx & 63;
        At[k*68 + r] = emb[(i0 + r)*64 + k];
        Bt[k*68 + r] = emb[(j0 + r)*64 + k];
    }
    __syncthreads();
    int tx = tid & 15, ty = tid >> 4;
    int r0 = ty * 4, c0 = tx * 4;
    float acc[4][4] = {};
#pragma unroll 8
    for (int k = 0; k < 64; ++k) {
        float4 a4 = *(const float4*)&At[k*68 + r0];
        float4 b4 = *(const float4*)&Bt[k*68 + c0];
        float av[4] = {a4.x, a4.y, a4.z, a4.w};
        float bv[4] = {b4.x, b4.y, b4.z, b4.w};
#pragma unroll
        for (int r = 0; r < 4; ++r)
#pragma unroll
            for (int c = 0; c < 4; ++c)
                acc[r][c] = fmaf(av[r], bv[c], acc[r][c]);
    }
    float rnj[4];
#pragma unroll
    for (int c = 0; c < 4; ++c) rnj[c] = g_rnrm[j0 + c0 + c];
#pragma unroll
    for (int r = 0; r < 4; ++r) {
        float rni = g_rnrm[i0 + r0 + r];
        float4 o;
        o.x = acc[r][0] * rni * rnj[0];
        o.y = acc[r][1] * rni * rnj[1];
        o.z = acc[r][2] * rni * rnj[2];
        o.w = acc[r][3] * rni * rnj[3];
        *(float4*)&g_cos[(i0 + r0 + r)*Nn + j0 + c0] = o;
    }
}

// ---------------- K2: per-row top-20 (warp per row) ------------------------
__global__ void k2_topk() {
    int w    = blockIdx.x * (blockDim.x >> 5) + (threadIdx.x >> 5); // row
    int lane = threadIdx.x & 31;
    const float* row = g_cos + w * Nn;
    float v[16];
#pragma unroll
    for (int t = 0; t < 16; ++t) v[t] = row[t*32 + lane];
    float bv = v[0]; int bt = 0;
#pragma unroll
    for (int t = 1; t < 16; ++t) if (v[t] > bv) { bv = v[t]; bt = t; }
    for (int it = 0; it < KTOP; ++it) {
        float rv = bv; int ri = bt*32 + lane;
#pragma unroll
        for (int off = 16; off; off >>= 1) {
            float ov = __shfl_down_sync(FULLMASK, rv, off);
            int   oi = __shfl_down_sync(FULLMASK, ri, off);
            if (ov > rv || (ov == rv && oi < ri)) { rv = ov; ri = oi; }
        }
        ri = __shfl_sync(FULLMASK, ri, 0);
        if (lane == 0) g_topk[w*KTOP + it] = ri;
        if ((ri & 31) == lane) {
            int kt = ri >> 5;
#pragma unroll
            for (int t = 0; t < 16; ++t) if (t == kt) v[t] = -INFINITY;
            bv = v[0]; bt = 0;
#pragma unroll
            for (int t = 1; t < 16; ++t) if (v[t] > bv) { bv = v[t]; bt = t; }
        }
    }
}

// ---------------- K3: z = data @ fc_w^T + fc_b (65536x64x64) ---------------
__global__ void k3_zgemm(const float* __restrict__ data,
                         const float* __restrict__ fc_w,
                         const float* __restrict__ fc_b) {
    __shared__ float At[64*68];   // At[f][r] = data[m0+r][f]
    __shared__ float Wt[64*68];   // Wt[f][d] = fc_w[d][f]
    int m0 = blockIdx.x * 64;
    int tid = threadIdx.x;        // 256 threads
    for (int idx = tid; idx < 4096; idx += 256) {
        int r = idx >> 6, k = idx & 63;
        At[k*68 + r] = data[(m0 + r)*64 + k];
        Wt[k*68 + r] = fc_w[r*64 + k];
    }
    __syncthreads();
    int tx = tid & 15, ty = tid >> 4;
    int r0 = ty * 4, c0 = tx * 4;
    float acc[4][4] = {};
#pragma unroll 8
    for (int k = 0; k < 64; ++k) {
        float4 a4 = *(const float4*)&At[k*68 + r0];
        float4 b4 = *(const float4*)&Wt[k*68 + c0];
        float av[4] = {a4.x, a4.y, a4.z, a4.w};
        float bv[4] = {b4.x, b4.y, b4.z, b4.w};
#pragma unroll
        for (int r = 0; r < 4; ++r)
#pragma unroll
            for (int c = 0; c < 4; ++c)
                acc[r][c] = fmaf(av[r], bv[c], acc[r][c]);
    }
    float4 bias = *(const float4*)&fc_b[c0];
#pragma unroll
    for (int r = 0; r < 4; ++r) {
        float4 o;
        o.x = acc[r][0] + bias.x;
        o.y = acc[r][1] + bias.y;
        o.z = acc[r][2] + bias.z;
        o.w = acc[r][3] + bias.w;
        *(float4*)&g_z[(m0 + r0 + r)*64 + c0] = o;
    }
}

// ---------------- K4: attention + rst + BN partial stats -------------------
// One CTA per batch b. z[b] lives in smem (stride 65 floats: conflict-free
// both for row-wise dot (s_src/s_dst) and channel-wise gather (h phase)).
__global__ void k4_attn(const float* __restrict__ emb,
                        const float* __restrict__ attn_w,
                        const float* __restrict__ attn_b_p) {
    extern __shared__ float sm[];
    float* z_sm = sm;                    // 512*65
    float* ssrc = sm + 512*65;           // 512
    float* sdst = ssrc + 512;            // 512
    float* aw   = sdst + 512;            // 256
    float* ssum = aw + 256;              // 64
    float* ssq  = ssum + 64;             // 64

    int b = blockIdx.x, tid = threadIdx.x;   // 512 threads
    if (tid < 256) aw[tid] = attn_w[tid];
    else if (tid < 384) {
        int t = tid - 256;
        if (t < 64) ssum[t] = 0.f; else ssq[t - 64] = 0.f;
    }

    const float4* zg = (const float4*)(g_z + (size_t)b * Nn * Dd);
    for (int i4 = tid; i4 < 8192; i4 += 512) {
        float4 v = zg[i4];
        int n = i4 >> 4, k = (i4 & 15) << 2;
        float* p = &z_sm[n*65 + k];
        p[0] = v.x; p[1] = v.y; p[2] = v.z; p[3] = v.w;
    }
    __syncthreads();

    {   // s_src / s_dst per node (thread per node, conflict-free stride 65)
        int n = tid;
        float s1 = 0.f, s2 = 0.f;
#pragma unroll
        for (int k = 0; k < 64; ++k) {
            float zv = z_sm[n*65 + k];
            s1 = fmaf(zv, aw[k],       s1);
            s2 = fmaf(zv, aw[128 + k], s2);
        }
        ssrc[n] = s1 + g_esrc[n];
        sdst[n] = s2 + g_edst[n];
    }
    __syncthreads();

    const float ab = *attn_b_p;
    int w = tid >> 5, lane = tid & 31;
    float acc_s0 = 0.f, acc_q0 = 0.f, acc_s1 = 0.f, acc_q1 = 0.f;

    for (int r = 0; r < 32; ++r) {
        int d = w * 32 + r;
        float sd = sdst[d];
        int srcj = 0; float sc = -INFINITY;
        if (lane < KTOP) {
            int g = d + (lane << 9);           // edge id e = d + 512*j
            srcj = g_topk[g];                   // src = topk_flat[e]
            float x = ssrc[srcj] + sd + ab;
            sc = (x > 0.f) ? x : NEG_SLOPE * x;
        }
        float m = sc;
#pragma unroll
        for (int off = 16; off; off >>= 1)
            m = fmaxf(m, __shfl_xor_sync(FULLMASK, m, off));
        float p = (lane < KTOP) ? expf(sc - m) : 0.f;
        float psum = p;
#pragma unroll
        for (int off = 16; off; off >>= 1)
            psum += __shfl_xor_sync(FULLMASK, psum, off);
        float alpha = p / psum;

        float h0 = 0.f, h1 = 0.f;
#pragma unroll
        for (int j = 0; j < KTOP; ++j) {
            float a = __shfl_sync(FULLMASK, alpha, j);
            int   s = __shfl_sync(FULLMASK, srcj,  j);
            h0 = fmaf(a, z_sm[s*65 + lane],      h0);
            h1 = fmaf(a, z_sm[s*65 + 32 + lane], h1);
        }
        float e0 = emb[d*64 + lane];
        float e1 = emb[d*64 + 32 + lane];
        float r0 = h0 * e0, r1 = h1 * e1;
        size_t ro = ((size_t)b * Nn + d) * Dd;
        g_rst[ro + lane]      = r0;
        g_rst[ro + 32 + lane] = r1;
        acc_s0 += r0; acc_q0 = fmaf(r0, r0, acc_q0);
        acc_s1 += r1; acc_q1 = fmaf(r1, r1, acc_q1);
    }
    atomicAdd(&ssum[lane],      acc_s0);
    atomicAdd(&ssum[lane + 32], acc_s1);
    atomicAdd(&ssq[lane],       acc_q0);
    atomicAdd(&ssq[lane + 32],  acc_q1);
    __syncthreads();
    if (tid < 64) {
        atomicAdd(&g_sum[tid],   ssum[tid]);
        atomicAdd(&g_sumsq[tid], ssq[tid]);
    }
}

// ---------------- K5: finalize BN stats ------------------------------------
__global__ void k5_bnstats(const float* __restrict__ gamma,
                           const float* __restrict__ beta) {
    int t = threadIdx.x;  // 64
    const float inv_n = 1.0f / (float)(Bsz * Nn);
    float mu  = g_sum[t] * inv_n;
    float var = g_sumsq[t] * inv_n - mu * mu;
    float sc  = gamma[t] / sqrtf(var + BN_EPS);
    g_scale[t] = sc;
    g_shift[t] = beta[t] - mu * sc;
}

// ---------------- K6: BN + relu + output projection ------------------------
__global__ void k6_out(const float* __restrict__ out_w,
                       const float* __restrict__ out_b_p,
                       float* __restrict__ out) {
    int w    = blockIdx.x * (blockDim.x >> 5) + (threadIdx.x >> 5); // row b*N+n
    int lane = threadIdx.x & 31;
    const float* r = g_rst + (size_t)w * Dd;
    float v0 = fmaf(r[lane],      g_scale[lane],      g_shift[lane]);
    float v1 = fmaf(r[lane + 32], g_scale[lane + 32], g_shift[lane + 32]);
    v0 = fmaxf(v0, 0.f) * out_w[lane];
    v1 = fmaxf(v1, 0.f) * out_w[lane + 32];
    float s = v0 + v1;
#pragma unroll
    for (int off = 16; off; off >>= 1)
        s += __shfl_down_sync(FULLMASK, s, off);
    if (lane == 0) out[w] = s + *out_b_p;
}

// ---------------- launch ----------------------------------------------------
extern "C" void kernel_launch(void* const* d_in, const int* in_sizes, int n_in,
                              void* d_out, int out_size) {
    const float* data     = (const float*)d_in[0];
    const float* emb      = (const float*)d_in[1];
    const float* fc_w     = (const float*)d_in[2];
    const float* fc_b     = (const float*)d_in[3];
    const float* attn_w   = (const float*)d_in[4];
    const float* attn_b   = (const float*)d_in[5];
    const float* bn_gamma = (const float*)d_in[6];
    const float* bn_beta  = (const float*)d_in[7];
    const float* out_w    = (const float*)d_in[8];
    const float* out_b    = (const float*)d_in[9];
    float* out = (float*)d_out;

    const int K4_SMEM = (512*65 + 512 + 512 + 256 + 128) * (int)sizeof(float);
    cudaFuncSetAttribute(k4_attn, cudaFuncAttributeMaxDynamicSharedMemorySize,
                         K4_SMEM);

    k0_prep   <<<1, 512>>>(emb, attn_w);
    k1_cos    <<<dim3(8, 8), 256>>>(emb);
    k2_topk   <<<32, 512>>>();
    k3_zgemm  <<<1024, 256>>>(data, fc_w, fc_b);
    k4_attn   <<<Bsz, 512, K4_SMEM>>>(emb, attn_w, attn_b);
    k5_bnstats<<<1, 64>>>(bn_gamma, bn_beta);
    k6_out    <<<Bsz * Nn / 16, 512>>>(out_w, out_b, out);
}

// round 2
// speedup vs baseline: 1.0616x; 1.0616x over previous
#include <cuda_runtime.h>
#include <math.h>

#define Bsz 128
#define Nn  512
#define Dd  64
#define KTOP 20
#define FULLMASK 0xFFFFFFFFu
#define NEG_SLOPE 0.2f
#define BN_EPS 1e-5f

typedef unsigned long long ull;

// ---------------- scratch (device globals; no allocations) ----------------
__device__ __align__(16) float g_rst[Bsz*Nn*Dd];   // 16.7 MB
__device__ __align__(16) float g_cos[Nn*Nn];       // 1 MB
__device__ __align__(16) float g_wT[Dd*Dd];        // fc_w transposed: wT[f][d]
__device__ int   g_topk[Nn*KTOP];
__device__ float g_rnrm[Nn];
__device__ float g_esrc[Nn];
__device__ float g_edst[Nn];
__device__ __align__(16) float g_sum[Dd];
__device__ __align__(16) float g_sumsq[Dd];
__device__ __align__(16) float g_scale[Dd];
__device__ __align__(16) float g_shift[Dd];

// ---------------- f32x2 packed helpers (PTX-only on sm_103a) ---------------
__device__ __forceinline__ ull pack2(float x, float y) {
    ull r; asm("mov.b64 %0, {%1, %2};" : "=l"(r) : "f"(x), "f"(y)); return r;
}
__device__ __forceinline__ void fma2(ull& d, ull a, ull b) {
    asm("fma.rn.f32x2 %0, %1, %2, %0;" : "+l"(d) : "l"(a), "l"(b));
}
__device__ __forceinline__ float2 unpack2(ull v) {
    float2 r; asm("mov.b64 {%0, %1}, %2;" : "=f"(r.x), "=f"(r.y) : "l"(v)); return r;
}

// ---------------- K0: per-node precompute + wT + zero accumulators ---------
__global__ void k0_prep(const float* __restrict__ emb,
                        const float* __restrict__ attn_w,
                        const float* __restrict__ fc_w) {
    int n = threadIdx.x;             // 512 threads
    if (n < Dd) { g_sum[n] = 0.f; g_sumsq[n] = 0.f; }
    // transpose fc_w (coalesced reads, scattered stores)
    for (int i = n; i < Dd*Dd; i += 512) {
        int d = i >> 6, f = i & 63;
        g_wT[f*64 + d] = fc_w[i];
    }
    const float* e = emb + n * Dd;
    float s = 0.f, es = 0.f, ed = 0.f;
#pragma unroll
    for (int k = 0; k < Dd; ++k) {
        float v = e[k];
        s  += v * v;
        es += v * attn_w[Dd + k];        // a_src, emb half
        ed += v * attn_w[3*Dd + k];      // a_dst, emb half
    }
    g_rnrm[n] = 1.0f / sqrtf(s);
    g_esrc[n] = es;
    g_edst[n] = ed;
}

// ---------------- K1: cosine Gram matrix (512x512x64 GEMM) ----------------
__global__ void k1_cos(const float* __restrict__ emb) {
    __shared__ float At[64*68];
    __shared__ float Bt[64*68];
    int i0 = blockIdx.y * 64, j0 = blockIdx.x * 64;
    int tid = threadIdx.x;           // 256 threads
    for (int idx = tid; idx < 4096; idx += 256) {
        int r = idx >> 6, k = idx & 63;
        At[k*68 + r] = emb[(i0 + r)*64 + k];
        Bt[k*68 + r] = emb[(j0 + r)*64 + k];
    }
    __syncthreads();
    int tx = tid & 15, ty = tid >> 4;
    int r0 = ty * 4, c0 = tx * 4;
    float acc[4][4] = {};
#pragma unroll 8
    for (int k = 0; k < 64; ++k) {
        float4 a4 = *(const float4*)&At[k*68 + r0];
        float4 b4 = *(const float4*)&Bt[k*68 + c0];
        float av[4] = {a4.x, a4.y, a4.z, a4.w};
        float bv[4] = {b4.x, b4.y, b4.z, b4.w};
#pragma unroll
        for (int r = 0; r < 4; ++r)
#pragma unroll
            for (int c = 0; c < 4; ++c)
                acc[r][c] = fmaf(av[r], bv[c], acc[r][c]);
    }
    float rnj[4];
#pragma unroll
    for (int c = 0; c < 4; ++c) rnj[c] = g_rnrm[j0 + c0 + c];
#pragma unroll
    for (int r = 0; r < 4; ++r) {
        float rni = g_rnrm[i0 + r0 + r];
        float4 o;
        o.x = acc[r][0] * rni * rnj[0];
        o.y = acc[r][1] * rni * rnj[1];
        o.z = acc[r][2] * rni * rnj[2];
        o.w = acc[r][3] * rni * rnj[3];
        *(float4*)&g_cos[(i0 + r0 + r)*Nn + j0 + c0] = o;
    }
}

// ---------------- K2: per-row top-20 (warp per row) ------------------------
__global__ void k2_topk() {
    int w    = blockIdx.x * (blockDim.x >> 5) + (threadIdx.x >> 5); // row
    int lane = threadIdx.x & 31;
    const float* row = g_cos + w * Nn;
    float v[16];
#pragma unroll
    for (int t = 0; t < 16; ++t) v[t] = row[t*32 + lane];
    float bv = v[0]; int bt = 0;
#pragma unroll
    for (int t = 1; t < 16; ++t) if (v[t] > bv) { bv = v[t]; bt = t; }
    for (int it = 0; it < KTOP; ++it) {
        float rv = bv; int ri = bt*32 + lane;
#pragma unroll
        for (int off = 16; off; off >>= 1) {
            float ov = __shfl_down_sync(FULLMASK, rv, off);
            int   oi = __shfl_down_sync(FULLMASK, ri, off);
            if (ov > rv || (ov == rv && oi < ri)) { rv = ov; ri = oi; }
        }
        ri = __shfl_sync(FULLMASK, ri, 0);
        if (lane == 0) g_topk[w*KTOP + it] = ri;
        if ((ri & 31) == lane) {
            int kt = ri >> 5;
#pragma unroll
            for (int t = 0; t < 16; ++t) if (t == kt) v[t] = -INFINITY;
            bv = v[0]; bt = 0;
#pragma unroll
            for (int t = 1; t < 16; ++t) if (v[t] > bv) { bv = v[t]; bt = t; }
        }
    }
}

// ---------------- K4: fused z-GEMM + attention + rst + BN stats ------------
// One CTA per batch b. z[b] computed in smem (f32x2 GEMM from staged data),
// then attention as before. z stride 65: conflict-free for both row dot and
// channel gather.
__global__ void __launch_bounds__(512, 1)
k4_fused(const float* __restrict__ data,
         const float* __restrict__ emb,
         const float* __restrict__ attn_w,
         const float* __restrict__ attn_b_p,
         const float* __restrict__ fc_b) {
    extern __shared__ float sm[];
    float* z_sm   = sm;                   // 512*65   = 33280
    float* dat_sm = z_sm + 512*65;        // 256*65   = 16640
    float* wT     = dat_sm + 256*65;      // 64*64    = 4096
    float* ssrc   = wT + 64*64;           // 512
    float* sdst   = ssrc + 512;           // 512
    float* aw     = sdst + 512;           // 256
    float* bias   = aw + 256;             // 64
    float* ssum   = bias + 64;            // 64
    float* ssq    = ssum + 64;            // 64

    int b = blockIdx.x, tid = threadIdx.x;   // 512 threads

    // prologue staging
    if (tid < 256) aw[tid] = attn_w[tid];
    else if (tid < 320) bias[tid-256] = fc_b[tid-256];
    else if (tid < 448) {
        int t = tid - 320;
        if (t < 64) ssum[t] = 0.f; else ssq[t-64] = 0.f;
    }
    for (int i = tid; i < 4096; i += 512) wT[i] = g_wT[i];   // conflict-free

    // ---- z GEMM: 2 chunks x 256 nodes ----
    int w = tid >> 5, lane = tid & 31;
    int cg = w & 3, q = w >> 2;             // 16 ch per thread, 4 node-quarters
    int d0 = cg * 16;
    int nA = q*64 + lane, nB = nA + 32;

    const float4* dg = (const float4*)(data + (size_t)b * Nn * Dd);
    for (int chunk = 0; chunk < 2; ++chunk) {
        // stage data chunk (256 x 64) row-major, stride 65
#pragma unroll
        for (int it = 0; it < 8; ++it) {
            int i4 = tid + it*512;
            float4 v = dg[chunk*4096 + i4];
            int n = i4 >> 4, f0 = (i4 & 15) << 2;
            float* p = &dat_sm[n*65 + f0];
            p[0] = v.x; p[1] = v.y; p[2] = v.z; p[3] = v.w;
        }
        __syncthreads();

        ull accA[8] = {0,0,0,0,0,0,0,0};
        ull accB[8] = {0,0,0,0,0,0,0,0};
        const float* dA = &dat_sm[nA*65];
        const float* dB = &dat_sm[nB*65];
#pragma unroll 4
        for (int f = 0; f < 64; ++f) {
            float a0 = dA[f], a1 = dB[f];
            ull pa = pack2(a0, a0), pb = pack2(a1, a1);
            const float4* wp = (const float4*)&wT[f*64 + d0];
            float4 w0 = wp[0], w1 = wp[1], w2 = wp[2], w3 = wp[3];
            ull q0 = pack2(w0.x, w0.y), q1 = pack2(w0.z, w0.w);
            ull q2 = pack2(w1.x, w1.y), q3 = pack2(w1.z, w1.w);
            ull q4 = pack2(w2.x, w2.y), q5 = pack2(w2.z, w2.w);
            ull q6 = pack2(w3.x, w3.y), q7 = pack2(w3.z, w3.w);
            fma2(accA[0], pa, q0); fma2(accA[1], pa, q1);
            fma2(accA[2], pa, q2); fma2(accA[3], pa, q3);
            fma2(accA[4], pa, q4); fma2(accA[5], pa, q5);
            fma2(accA[6], pa, q6); fma2(accA[7], pa, q7);
            fma2(accB[0], pb, q0); fma2(accB[1], pb, q1);
            fma2(accB[2], pb, q2); fma2(accB[3], pb, q3);
            fma2(accB[4], pb, q4); fma2(accB[5], pb, q5);
            fma2(accB[6], pb, q6); fma2(accB[7], pb, q7);
        }
        int ng = chunk * 256;
#pragma unroll
        for (int j = 0; j < 8; ++j) {
            float2 va = unpack2(accA[j]);
            float2 vb = unpack2(accB[j]);
            float b0 = bias[d0 + 2*j], b1 = bias[d0 + 2*j + 1];
            z_sm[(ng+nA)*65 + d0 + 2*j]     = va.x + b0;
            z_sm[(ng+nA)*65 + d0 + 2*j + 1] = va.y + b1;
            z_sm[(ng+nB)*65 + d0 + 2*j]     = vb.x + b0;
            z_sm[(ng+nB)*65 + d0 + 2*j + 1] = vb.y + b1;
        }
        __syncthreads();
    }

    // ---- s_src / s_dst per node ----
    {
        int n = tid;
        float s1 = 0.f, s2 = 0.f;
#pragma unroll
        for (int k = 0; k < 64; ++k) {
            float zv = z_sm[n*65 + k];
            s1 = fmaf(zv, aw[k],       s1);
            s2 = fmaf(zv, aw[128 + k], s2);
        }
        ssrc[n] = s1 + g_esrc[n];
        sdst[n] = s2 + g_edst[n];
    }
    __syncthreads();

    // ---- attention gather ----
    const float ab = *attn_b_p;
    float acc_s0 = 0.f, acc_q0 = 0.f, acc_s1 = 0.f, acc_q1 = 0.f;

    for (int r = 0; r < 32; ++r) {
        int d = w * 32 + r;
        float sd = sdst[d];
        int srcj = 0; float sc = -INFINITY;
        if (lane < KTOP) {
            int g = d + (lane << 9);           // edge id e = d + 512*j
            srcj = g_topk[g];                   // src = topk_flat[e]
            float x = ssrc[srcj] + sd + ab;
            sc = (x > 0.f) ? x : NEG_SLOPE * x;
        }
        float m = sc;
#pragma unroll
        for (int off = 16; off; off >>= 1)
            m = fmaxf(m, __shfl_xor_sync(FULLMASK, m, off));
        float p = (lane < KTOP) ? expf(sc - m) : 0.f;
        float psum = p;
#pragma unroll
        for (int off = 16; off; off >>= 1)
            psum += __shfl_xor_sync(FULLMASK, psum, off);
        float alpha = p / psum;

        float h0 = 0.f, h1 = 0.f;
#pragma unroll
        for (int j = 0; j < KTOP; ++j) {
            float a = __shfl_sync(FULLMASK, alpha, j);
            int   s = __shfl_sync(FULLMASK, srcj,  j);
            h0 = fmaf(a, z_sm[s*65 + lane],      h0);
            h1 = fmaf(a, z_sm[s*65 + 32 + lane], h1);
        }
        float e0 = emb[d*64 + lane];
        float e1 = emb[d*64 + 32 + lane];
        float r0 = h0 * e0, r1 = h1 * e1;
        size_t ro = ((size_t)b * Nn + d) * Dd;
        g_rst[ro + lane]      = r0;
        g_rst[ro + 32 + lane] = r1;
        acc_s0 += r0; acc_q0 = fmaf(r0, r0, acc_q0);
        acc_s1 += r1; acc_q1 = fmaf(r1, r1, acc_q1);
    }
    atomicAdd(&ssum[lane],      acc_s0);
    atomicAdd(&ssum[lane + 32], acc_s1);
    atomicAdd(&ssq[lane],       acc_q0);
    atomicAdd(&ssq[lane + 32],  acc_q1);
    __syncthreads();
    if (tid < 64) {
        atomicAdd(&g_sum[tid],   ssum[tid]);
        atomicAdd(&g_sumsq[tid], ssq[tid]);
    }
}

// ---------------- K5: finalize BN stats ------------------------------------
__global__ void k5_bnstats(const float* __restrict__ gamma,
                           const float* __restrict__ beta) {
    int t = threadIdx.x;  // 64
    const float inv_n = 1.0f / (float)(Bsz * Nn);
    float mu  = g_sum[t] * inv_n;
    float var = g_sumsq[t] * inv_n - mu * mu;
    float sc  = gamma[t] / sqrtf(var + BN_EPS);
    g_scale[t] = sc;
    g_shift[t] = beta[t] - mu * sc;
}

// ---------------- K6: BN + relu + output projection (float4, 2 rows/warp) --
__global__ void k6_out(const float* __restrict__ out_w,
                       const float* __restrict__ out_b_p,
                       float* __restrict__ out) {
    int gw   = blockIdx.x * (blockDim.x >> 5) + (threadIdx.x >> 5);
    int lane = threadIdx.x & 31;
    int g = lane >> 4, l16 = lane & 15;
    int row = gw * 2 + g;
    const float4* r4 = (const float4*)(g_rst + (size_t)row * Dd);
    float4 v  = r4[l16];
    float4 sc = ((const float4*)g_scale)[l16];
    float4 sh = ((const float4*)g_shift)[l16];
    float4 ww = ((const float4*)out_w)[l16];
    float s = fmaxf(fmaf(v.x, sc.x, sh.x), 0.f) * ww.x
            + fmaxf(fmaf(v.y, sc.y, sh.y), 0.f) * ww.y
            + fmaxf(fmaf(v.z, sc.z, sh.z), 0.f) * ww.z
            + fmaxf(fmaf(v.w, sc.w, sh.w), 0.f) * ww.w;
#pragma unroll
    for (int off = 8; off; off >>= 1)
        s += __shfl_xor_sync(FULLMASK, s, off);
    if (l16 == 0) out[row] = s + *out_b_p;
}

// ---------------- launch ----------------------------------------------------
extern "C" void kernel_launch(void* const* d_in, const int* in_sizes, int n_in,
                              void* d_out, int out_size) {
    const float* data     = (const float*)d_in[0];
    const float* emb      = (const float*)d_in[1];
    const float* fc_w     = (const float*)d_in[2];
    const float* fc_b     = (const float*)d_in[3];
    const float* attn_w   = (const float*)d_in[4];
    const float* attn_b   = (const float*)d_in[5];
    const float* bn_gamma = (const float*)d_in[6];
    const float* bn_beta  = (const float*)d_in[7];
    const float* out_w    = (const float*)d_in[8];
    const float* out_b    = (const float*)d_in[9];
    float* out = (float*)d_out;

    const int K4_SMEM = (512*65 + 256*65 + 64*64 + 512 + 512 + 256 + 64 + 128)
                        * (int)sizeof(float);
    cudaFuncSetAttribute(k4_fused, cudaFuncAttributeMaxDynamicSharedMemorySize,
                         K4_SMEM);

    k0_prep   <<<1, 512>>>(emb, attn_w, fc_w);
    k1_cos    <<<dim3(8, 8), 256>>>(emb);
    k2_topk   <<<32, 512>>>();
    k4_fused  <<<Bsz, 512, K4_SMEM>>>(data, emb, attn_w, attn_b, fc_b);
    k5_bnstats<<<1, 64>>>(bn_gamma, bn_beta);
    k6_out    <<<Bsz * Nn / 32, 512>>>(out_w, out_b, out);
}